// round 16
// baseline (speedup 1.0000x reference)
#include <cuda_runtime.h>
#include <cuda_bf16.h>
#include <math.h>
#include <stdint.h>

#define BATCH 262144
#define HID 512
#define NDIM 12
#define TRI 78
#define OUTC 79

typedef __nv_bfloat16 bf16;
typedef __nv_bfloat162 bf162;

// h1: plain bf16 rows 512 wide.
// h2: plain bf16 rows 512 wide.
// W2: packed hi/lo rows 1024 wide: (k/32)*64 + k%32 (hi), +32 (lo). rows = n.
// W3: packed hi/lo rows 1024 wide (rows n, zero-pad n >= 79).
__device__ bf16 g_h1[(size_t)BATCH * 512];     // 256 MB
__device__ bf16 g_h2[(size_t)BATCH * 512];     // 256 MB
__device__ bf16 g_w2pk[(size_t)HID * 1024];    // 1 MB
__device__ bf16 g_w3pk[(size_t)96 * 1024];     // 192 KB

// tri index -> (i, j) lookup for the 78 lower-tri entries
__device__ __constant__ int8_t TRI2I[TRI] = {
    0,1,1,2,2,2,3,3,3,3,4,4,4,4,4,5,5,5,5,5,5,6,6,6,6,6,6,6,
    7,7,7,7,7,7,7,7,8,8,8,8,8,8,8,8,8,9,9,9,9,9,9,9,9,9,9,
    10,10,10,10,10,10,10,10,10,10,10,11,11,11,11,11,11,11,11,11,11,11,11};
__device__ __constant__ int8_t TRI2J[TRI] = {
    0,0,1,0,1,2,0,1,2,3,0,1,2,3,4,0,1,2,3,4,5,0,1,2,3,4,5,6,
    0,1,2,3,4,5,6,7,0,1,2,3,4,5,6,7,8,0,1,2,3,4,5,6,7,8,9,
    0,1,2,3,4,5,6,7,8,9,10,0,1,2,3,4,5,6,7,8,9,10,11};

#define SWZ(o) ((o) ^ (((o) >> 3) & 0x70))

__device__ __forceinline__ uint32_t smem_u32(const void* p) {
    uint32_t a;
    asm("{ .reg .u64 t; cvta.to.shared.u64 t, %1; cvt.u32.u64 %0, t; }"
        : "=r"(a) : "l"(p));
    return a;
}
__device__ __forceinline__ void cp16(uint32_t dst, const void* src) {
    asm volatile("cp.async.cg.shared.global [%0], [%1], 16;"
                 :: "r"(dst), "l"(src));
}
#define CP_COMMIT() asm volatile("cp.async.commit_group;" ::: "memory")
#define CP_WAIT(n)  asm volatile("cp.async.wait_group %0;" :: "n"(n) : "memory")

#define LDSM_X4(r0, r1, r2, r3, a)                                            \
    asm volatile("ldmatrix.sync.aligned.m8n8.x4.shared.b16 {%0,%1,%2,%3}, [%4];" \
                 : "=r"(r0), "=r"(r1), "=r"(r2), "=r"(r3) : "r"(a))
#define LDSM_X2(r0, r1, a)                                                    \
    asm volatile("ldmatrix.sync.aligned.m8n8.x2.shared.b16 {%0,%1}, [%2];"    \
                 : "=r"(r0), "=r"(r1) : "r"(a))
#define MMA_BF16(c, a, b)                                                     \
    asm volatile("mma.sync.aligned.m16n8k16.row.col.f32.bf16.bf16.f32 "       \
                 "{%0,%1,%2,%3}, {%4,%5,%6,%7}, {%8,%9}, {%0,%1,%2,%3};"      \
                 : "+f"((c)[0]), "+f"((c)[1]), "+f"((c)[2]), "+f"((c)[3])     \
                 : "r"((a)[0]), "r"((a)[1]), "r"((a)[2]), "r"((a)[3]),        \
                   "r"((b)[0]), "r"((b)[1]))

static __device__ __forceinline__ float softplusf(float v) {
    return (v > 20.f) ? v : __logf(1.f + __expf(v));
}
static __device__ __forceinline__ int pkoff(int k) {
    return ((k >> 5) << 6) + (k & 31);
}

// ---------------- prep kernel: l1 (blocks 0..1023) + conv_w2 + conv_w3 ------
__global__ __launch_bounds__(256) void prep_kernel(
    const float* __restrict__ x, const float* __restrict__ W1,
    const float* __restrict__ b1, const float* __restrict__ W2,
    const float* __restrict__ W3, bf16* __restrict__ hp)
{
    const int bid = blockIdx.x;
    const int tid = threadIdx.x;

    if (bid >= 1024) {
        if (bid < 2048) {                      // conv_w2: 512x512
            int t = (bid - 1024) * 256 + tid;
            int n = t >> 9, k = t & 511;
            float v = W2[(size_t)k * HID + n];
            bf16 h = __float2bfloat16(v);
            size_t o = (size_t)n * 1024 + pkoff(k);
            g_w2pk[o] = h;
            g_w2pk[o + 32] = __float2bfloat16(v - __bfloat162float(h));
        } else {                               // conv_w3: 96x512
            int t = (bid - 2048) * 256 + tid;
            int n = t >> 9, k = t & 511;
            float v = (n < OUTC) ? W3[(size_t)k * OUTC + n] : 0.f;
            bf16 h = __float2bfloat16(v);
            size_t o = (size_t)n * 1024 + pkoff(k);
            g_w3pk[o] = h;
            g_w3pk[o + 32] = __float2bfloat16(v - __bfloat162float(h));
        }
        return;
    }

    // ---- layer 1: 256 rows per block ----
    __shared__ float W1s[NDIM][HID];
    __shared__ float b1s[HID];
    __shared__ float xs[256][13];
    const int b0 = bid * 256;

    for (int i = tid; i < NDIM * HID; i += 256) W1s[i / HID][i % HID] = W1[i];
    for (int i = tid; i < HID; i += 256) b1s[i] = b1[i];
    for (int i = tid; i < 256 * NDIM; i += 256)
        xs[i / NDIM][i % NDIM] = x[(size_t)b0 * NDIM + i];
    __syncthreads();

#pragma unroll 4
    for (int it = 0; it < 64; ++it) {
        int p = tid + it * 256;
        int r = p >> 6;
        int c = (p & 63) * 8;
        float a[8];
#pragma unroll
        for (int j = 0; j < 8; ++j) a[j] = b1s[c + j];
#pragma unroll
        for (int k = 0; k < NDIM; ++k) {
            float xv = xs[r][k];
#pragma unroll
            for (int j = 0; j < 8; ++j)
                a[j] = fmaf(xv, W1s[k][c + j], a[j]);
        }
        __align__(16) bf162 hb[4];
#pragma unroll
        for (int j = 0; j < 4; ++j)
            hb[j] = __halves2bfloat162(
                __float2bfloat16(fmaxf(a[2 * j], 0.f)),
                __float2bfloat16(fmaxf(a[2 * j + 1], 0.f)));
        *(uint4*)(hp + (size_t)(b0 + r) * 512 + c) = *(uint4*)hb;
    }
}

// ---------------- GEMM2 (R12-proven): A plain bf16, B split W2; 2-term ------
// k-chunk 64. smem: A0@0(16K), A1@16K, B0@32K(32K), B1@64K; 96K (2 CTAs/SM).
__global__ __launch_bounds__(256, 2) void gemm2(
    const bf16* __restrict__ A, const bf16* __restrict__ Bpk,
    const float* __restrict__ bias, bf16* __restrict__ O)
{
    extern __shared__ char smem[];
    const uint32_t sb = smem_u32(smem);
    const int tid = threadIdx.x;
    const int lane = tid & 31;
    const int wid = tid >> 5;
    const int wm = wid >> 2;        // 0..1, m band of 64
    const int wn = wid & 3;         // 0..3, n band of 32
    const int m0 = blockIdx.y * 128;
    const int n0 = blockIdx.x * 128;

    float acc[4][4][4];
#pragma unroll
    for (int i = 0; i < 4; i++)
#pragma unroll
        for (int j = 0; j < 4; j++)
#pragma unroll
            for (int k = 0; k < 4; k++) acc[i][j][k] = 0.f;

    const bf16* Abase = A + (size_t)m0 * 512;
    const bf16* Bbase = Bpk + (size_t)n0 * 1024;

    auto load_chunk = [&](int c, int buf) {
        uint32_t ab = sb + buf * 16384;
        uint32_t bb = sb + 32768 + buf * 32768;
        const bf16* As = Abase + c * 64;
        const bf16* Bs = Bbase + c * 128;
#pragma unroll
        for (int it = 0; it < 12; ++it) {
            int u = tid + it * 256;              // 0..3071
            if (u < 1024) {                      // A: 128 rows x 8 units
                int r = u >> 3, q = u & 7;
                cp16(ab + SWZ(r * 128 + q * 16), As + (size_t)r * 512 + q * 8);
            } else {                             // B: 128 rows x 16 units
                int v = u - 1024;
                int r = v >> 4, q = v & 15;
                int sub = q >> 3, qi = q & 7;
                cp16(bb + sub * 16384 + SWZ(r * 128 + qi * 16),
                     Bs + (size_t)r * 1024 + sub * 64 + qi * 8);
            }
        }
        CP_COMMIT();
    };

    load_chunk(0, 0);

    for (int c = 0; c < 8; ++c) {
        CP_WAIT(0);
        __syncthreads();
        if (c < 7) load_chunk(c + 1, (c + 1) & 1);

        const int buf = c & 1;
        const uint32_t ab = sb + buf * 16384;
#pragma unroll
        for (int sub = 0; sub < 2; ++sub) {
            const uint32_t bb = sb + 32768 + buf * 32768 + sub * 16384;
#pragma unroll
            for (int ks = 0; ks < 2; ++ks) {
                uint32_t bfr[2][4][2];
                const int brow0 = wn * 32 + (lane & 7);
                const int bsel = (lane >> 3) & 1;
#pragma unroll
                for (int pl = 0; pl < 2; ++pl)
#pragma unroll
                    for (int nt = 0; nt < 4; ++nt) {
                        int row = brow0 + nt * 8;
                        int seg = pl * 4 + ks * 2 + bsel;
                        LDSM_X2(bfr[pl][nt][0], bfr[pl][nt][1],
                                bb + row * 128 + ((seg ^ (row & 7)) << 4));
                    }
#pragma unroll
                for (int mt = 0; mt < 4; ++mt) {
                    uint32_t afr[4];
                    const int arow = wm * 64 + mt * 16 + (lane & 15);
                    const int asel = lane >> 4;
                    int seg = sub * 4 + ks * 2 + asel;
                    LDSM_X4(afr[0], afr[1], afr[2], afr[3],
                            ab + arow * 128 + ((seg ^ (arow & 7)) << 4));
#pragma unroll
                    for (int nt = 0; nt < 4; ++nt)
                        MMA_BF16(acc[mt][nt], afr, bfr[0][nt]);   // A*Whi
#pragma unroll
                    for (int nt = 0; nt < 4; ++nt)
                        MMA_BF16(acc[mt][nt], afr, bfr[1][nt]);   // A*Wlo
                }
            }
        }
        __syncthreads();
    }

    // epilogue: bias + relu -> plain bf16 h2
    const int r0 = wm * 64 + (lane >> 2);
    const int c0 = wn * 32 + (lane & 3) * 2;
#pragma unroll
    for (int mt = 0; mt < 4; ++mt)
#pragma unroll
        for (int nt = 0; nt < 4; ++nt) {
            const int gc = n0 + c0 + nt * 8;
            const float bb0 = __ldg(bias + gc);
            const float bb1 = __ldg(bias + gc + 1);
#pragma unroll
            for (int h = 0; h < 2; ++h) {
                const int row = m0 + r0 + mt * 16 + 8 * h;
                float v0 = fmaxf(acc[mt][nt][2 * h] + bb0, 0.f);
                float v1 = fmaxf(acc[mt][nt][2 * h + 1] + bb1, 0.f);
                *(bf162*)(O + (size_t)row * 512 + gc) =
                    __halves2bfloat162(__float2bfloat16(v0), __float2bfloat16(v1));
            }
        }
}

// ---------------- GEMM3: plain A, split W3, N-tile 96; dense-L MMT ----------
// smem: A0@0(16K), A1@16K, B0@32K(24K), B1@56K; total 80K (2 CTAs/SM).
// Epilogue stage: dense L [128][148] floats (16B-aligned rows), 75.8KB.
#define LPITCH 148
__global__ __launch_bounds__(256, 2) void gemm3_mmt(
    const bf16* __restrict__ A, const bf16* __restrict__ Bpk,
    const float* __restrict__ bias, float* __restrict__ dst)
{
    extern __shared__ char smem[];
    const uint32_t sb = smem_u32(smem);
    const int tid = threadIdx.x;
    const int lane = tid & 31;
    const int wid = tid >> 5;
    const int wm = wid >> 2;        // 0..1 (m band of 64)
    const int wn = wid & 3;         // 0..3 (n band of 24)
    const int m0 = blockIdx.y * 128;

    float acc[4][3][4];
#pragma unroll
    for (int i = 0; i < 4; i++)
#pragma unroll
        for (int j = 0; j < 3; j++)
#pragma unroll
            for (int k = 0; k < 4; k++) acc[i][j][k] = 0.f;

    const bf16* Abase = A + (size_t)m0 * 512;

    auto load_chunk = [&](int c, int buf) {
        uint32_t ab = sb + buf * 16384;
        uint32_t bb = sb + 32768 + buf * 24576;
        const bf16* As = Abase + c * 64;
        const bf16* Bs = Bpk + c * 128;
#pragma unroll
        for (int it = 0; it < 10; ++it) {
            int u = tid + it * 256;              // 0..2559
            if (u < 1024) {                      // A: 128 rows x 8 units
                int r = u >> 3, q = u & 7;
                cp16(ab + SWZ(r * 128 + q * 16), As + (size_t)r * 512 + q * 8);
            } else {                             // B: 96 rows x 16 units
                int v = u - 1024;
                int r = v >> 4, q = v & 15;
                int sub = q >> 3, qi = q & 7;
                cp16(bb + sub * 12288 + SWZ(r * 128 + qi * 16),
                     Bs + (size_t)r * 1024 + sub * 64 + qi * 8);
            }
        }
        CP_COMMIT();
    };

    load_chunk(0, 0);

    for (int c = 0; c < 8; ++c) {
        CP_WAIT(0);
        __syncthreads();
        if (c < 7) load_chunk(c + 1, (c + 1) & 1);

        const int buf = c & 1;
        const uint32_t ab = sb + buf * 16384;
#pragma unroll
        for (int sub = 0; sub < 2; ++sub) {
            const uint32_t bb = sb + 32768 + buf * 24576 + sub * 12288;
#pragma unroll
            for (int ks = 0; ks < 2; ++ks) {
                uint32_t bfr[2][3][2];
                const int brow0 = wn * 24 + (lane & 7);
                const int bsel = (lane >> 3) & 1;
#pragma unroll
                for (int pl = 0; pl < 2; ++pl)
#pragma unroll
                    for (int nt = 0; nt < 3; ++nt) {
                        int row = brow0 + nt * 8;
                        int seg = pl * 4 + ks * 2 + bsel;
                        LDSM_X2(bfr[pl][nt][0], bfr[pl][nt][1],
                                bb + row * 128 + ((seg ^ (row & 7)) << 4));
                    }
#pragma unroll
                for (int mt = 0; mt < 4; ++mt) {
                    uint32_t afr[4];
                    const int arow = wm * 64 + mt * 16 + (lane & 15);
                    const int asel = lane >> 4;
                    int seg = sub * 4 + ks * 2 + asel;
                    LDSM_X4(afr[0], afr[1], afr[2], afr[3],
                            ab + arow * 128 + ((seg ^ (arow & 7)) << 4));
#pragma unroll
                    for (int nt = 0; nt < 3; ++nt)
                        MMA_BF16(acc[mt][nt], afr, bfr[0][nt]);   // A*hi
#pragma unroll
                    for (int nt = 0; nt < 3; ++nt)
                        MMA_BF16(acc[mt][nt], afr, bfr[1][nt]);   // A*lo
                }
            }
        }
        __syncthreads();
    }

    // ---- zero dense-L stage, then scatter softplus outputs ----
    float* stage = (float*)smem;     // [128][LPITCH]
    for (int i = tid; i < 128 * 144; i += 256)
        stage[(i / 144) * LPITCH + (i % 144)] = 0.f;
    __syncthreads();

    const int r0 = wm * 64 + (lane >> 2);
    const int c0 = wn * 24 + (lane & 3) * 2;
#pragma unroll
    for (int mt = 0; mt < 4; ++mt)
#pragma unroll
        for (int nt = 0; nt < 3; ++nt) {
            const int col = c0 + nt * 8;
            if (col >= 80) continue;
#pragma unroll
            for (int h = 0; h < 2; ++h) {
                const int row = r0 + mt * 16 + 8 * h;
#pragma unroll
                for (int e = 0; e < 2; ++e) {
                    const int cc = col + e;
                    if (cc > TRI) continue;
                    float v = softplusf(acc[mt][nt][2 * h + e] + __ldg(bias + cc));
                    int off = (cc == TRI) ? 144
                                          : (TRI2I[cc] * 12 + TRI2J[cc]);
                    stage[row * LPITCH + off] = v;
                }
            }
        }
    __syncthreads();

    // ---- MMT: dense 12x12, branch-free; item = (row, ii) ----
    for (int item = tid; item < 128 * 12; item += 256) {
        const int r = item / 12;
        const int ii = item - r * 12;
        const float* Lr = stage + r * LPITCH;
        float li[12];
#pragma unroll
        for (int j = 0; j < 12; ++j) li[j] = Lr[ii * 12 + j];
        __align__(16) float o[12];
#pragma unroll
        for (int kk = 0; kk < 12; ++kk) {
            const float* Lk = Lr + kk * 12;
            float a = 0.f;
#pragma unroll
            for (int j = 0; j < 12; ++j) a = fmaf(li[j], Lk[j], a);
            o[kk] = a;
        }
        float* drow = dst + (size_t)(m0 + r) * 144 + ii * 12;
        *(float4*)(drow)     = ((float4*)o)[0];
        *(float4*)(drow + 4) = ((float4*)o)[1];
        *(float4*)(drow + 8) = ((float4*)o)[2];
    }
    if (tid < 128)
        dst[(size_t)BATCH * 144 + m0 + tid] = stage[tid * LPITCH + 144];
}

// ---------------- launch ----------------------------------------------------
extern "C" void kernel_launch(void* const* d_in, const int* in_sizes, int n_in,
                              void* d_out, int out_size)
{
    const float* x  = (const float*)d_in[0];
    const float* W1 = (const float*)d_in[1];
    const float* b1 = (const float*)d_in[2];
    const float* W2 = (const float*)d_in[3];
    const float* b2 = (const float*)d_in[4];
    const float* W3 = (const float*)d_in[5];
    const float* b3 = (const float*)d_in[6];
    float* out = (float*)d_out;

    bf16 *h1, *h2, *w2pk, *w3pk;
    cudaGetSymbolAddress((void**)&h1, g_h1);
    cudaGetSymbolAddress((void**)&h2, g_h2);
    cudaGetSymbolAddress((void**)&w2pk, g_w2pk);
    cudaGetSymbolAddress((void**)&w3pk, g_w3pk);

    // prep: l1 (1024 blocks) + conv_w2 (1024) + conv_w3 (192)
    prep_kernel<<<2240, 256>>>(x, W1, b1, W2, W3, h1);

    constexpr int SMEM2 = 98304;         // 2x16K A + 2x32K B
    constexpr int SMEM3 = 81920;         // 2x16K A + 2x24K B
    cudaFuncSetAttribute(gemm2,
                         cudaFuncAttributeMaxDynamicSharedMemorySize, SMEM2);
    cudaFuncSetAttribute(gemm3_mmt,
                         cudaFuncAttributeMaxDynamicSharedMemorySize, SMEM3);

    gemm2<<<dim3(4, BATCH / 128), 256, SMEM2>>>(h1, w2pk, b2, h2);
    gemm3_mmt<<<dim3(1, BATCH / 128), 256, SMEM3>>>(h2, w3pk, b3, out);
}

// round 17
// speedup vs baseline: 1.4270x; 1.4270x over previous
#include <cuda_runtime.h>
#include <cuda_bf16.h>
#include <math.h>
#include <stdint.h>

#define BATCH 262144
#define HID 512
#define NDIM 12
#define TRI 78
#define OUTC 79

typedef __nv_bfloat16 bf16;
typedef __nv_bfloat162 bf162;

// h1: plain bf16 rows 512 wide.
// h2: plain bf16 rows 512 wide.
// W2: packed hi/lo rows 1024 wide: (k/32)*64 + k%32 (hi), +32 (lo). rows = n.
// W3: packed hi/lo rows 1024 wide (rows n, zero-pad n >= 79).
__device__ bf16 g_h1[(size_t)BATCH * 512];     // 256 MB
__device__ bf16 g_h2[(size_t)BATCH * 512];     // 256 MB
__device__ bf16 g_w2pk[(size_t)HID * 1024];    // 1 MB
__device__ bf16 g_w3pk[(size_t)96 * 1024];     // 192 KB

#define SWZ(o) ((o) ^ (((o) >> 3) & 0x70))

__device__ __forceinline__ uint32_t smem_u32(const void* p) {
    uint32_t a;
    asm("{ .reg .u64 t; cvta.to.shared.u64 t, %1; cvt.u32.u64 %0, t; }"
        : "=r"(a) : "l"(p));
    return a;
}
__device__ __forceinline__ void cp16(uint32_t dst, const void* src) {
    asm volatile("cp.async.cg.shared.global [%0], [%1], 16;"
                 :: "r"(dst), "l"(src));
}
#define CP_COMMIT() asm volatile("cp.async.commit_group;" ::: "memory")
#define CP_WAIT(n)  asm volatile("cp.async.wait_group %0;" :: "n"(n) : "memory")

#define LDSM_X4(r0, r1, r2, r3, a)                                            \
    asm volatile("ldmatrix.sync.aligned.m8n8.x4.shared.b16 {%0,%1,%2,%3}, [%4];" \
                 : "=r"(r0), "=r"(r1), "=r"(r2), "=r"(r3) : "r"(a))
#define LDSM_X2(r0, r1, a)                                                    \
    asm volatile("ldmatrix.sync.aligned.m8n8.x2.shared.b16 {%0,%1}, [%2];"    \
                 : "=r"(r0), "=r"(r1) : "r"(a))
#define MMA_BF16(c, a, b)                                                     \
    asm volatile("mma.sync.aligned.m16n8k16.row.col.f32.bf16.bf16.f32 "       \
                 "{%0,%1,%2,%3}, {%4,%5,%6,%7}, {%8,%9}, {%0,%1,%2,%3};"      \
                 : "+f"((c)[0]), "+f"((c)[1]), "+f"((c)[2]), "+f"((c)[3])     \
                 : "r"((a)[0]), "r"((a)[1]), "r"((a)[2]), "r"((a)[3]),        \
                   "r"((b)[0]), "r"((b)[1]))

static __device__ __forceinline__ float softplusf(float v) {
    return (v > 20.f) ? v : __logf(1.f + __expf(v));
}
static __device__ __forceinline__ int pkoff(int k) {
    return ((k >> 5) << 6) + (k & 31);
}

// ---------------- weight converters ----------------------------------------
__global__ __launch_bounds__(256) void conv_w2(const float* __restrict__ W2) {
    int t = blockIdx.x * 256 + threadIdx.x;        // < 512*512
    int n = t >> 9, k = t & 511;
    float v = W2[(size_t)k * HID + n];
    bf16 h = __float2bfloat16(v);
    size_t o = (size_t)n * 1024 + pkoff(k);
    g_w2pk[o] = h;
    g_w2pk[o + 32] = __float2bfloat16(v - __bfloat162float(h));
}
__global__ __launch_bounds__(256) void conv_w3(const float* __restrict__ W3) {
    int t = blockIdx.x * 256 + threadIdx.x;        // < 96*512
    int n = t >> 9, k = t & 511;
    float v = (n < OUTC) ? W3[(size_t)k * OUTC + n] : 0.f;
    bf16 h = __float2bfloat16(v);
    size_t o = (size_t)n * 1024 + pkoff(k);
    g_w3pk[o] = h;
    g_w3pk[o + 32] = __float2bfloat16(v - __bfloat162float(h));
}

// ---------------- layer 1 (K=12) — 256 rows/block, 16B stores ---------------
__global__ __launch_bounds__(256) void l1_kernel(
    const float* __restrict__ x, const float* __restrict__ W1,
    const float* __restrict__ b1, bf16* __restrict__ hp)
{
    __shared__ float W1s[NDIM][HID];
    __shared__ float b1s[HID];
    __shared__ float xs[256][13];
    const int tid = threadIdx.x;
    const int b0 = blockIdx.x * 256;

    for (int i = tid; i < NDIM * HID; i += 256) W1s[i / HID][i % HID] = W1[i];
    for (int i = tid; i < HID; i += 256) b1s[i] = b1[i];
    for (int i = tid; i < 256 * NDIM; i += 256)
        xs[i / NDIM][i % NDIM] = x[(size_t)b0 * NDIM + i];
    __syncthreads();

#pragma unroll 4
    for (int it = 0; it < 64; ++it) {
        int p = tid + it * 256;
        int r = p >> 6;
        int c = (p & 63) * 8;
        float a[8];
#pragma unroll
        for (int j = 0; j < 8; ++j) a[j] = b1s[c + j];
#pragma unroll
        for (int k = 0; k < NDIM; ++k) {
            float xv = xs[r][k];
#pragma unroll
            for (int j = 0; j < 8; ++j)
                a[j] = fmaf(xv, W1s[k][c + j], a[j]);
        }
        __align__(16) bf162 hb[4];
#pragma unroll
        for (int j = 0; j < 4; ++j)
            hb[j] = __halves2bfloat162(
                __float2bfloat16(fmaxf(a[2 * j], 0.f)),
                __float2bfloat16(fmaxf(a[2 * j + 1], 0.f)));
        *(uint4*)(hp + (size_t)(b0 + r) * 512 + c) = *(uint4*)hb;
    }
}

// ---------------- GEMM2 (R12-proven): A plain bf16, B split W2; 2-term ------
// k-chunk 64. smem: A0@0(16K), A1@16K, B0@32K(32K), B1@64K; 96K (2 CTAs/SM).
__global__ __launch_bounds__(256, 2) void gemm2(
    const bf16* __restrict__ A, const bf16* __restrict__ Bpk,
    const float* __restrict__ bias, bf16* __restrict__ O)
{
    extern __shared__ char smem[];
    const uint32_t sb = smem_u32(smem);
    const int tid = threadIdx.x;
    const int lane = tid & 31;
    const int wid = tid >> 5;
    const int wm = wid >> 2;        // 0..1, m band of 64
    const int wn = wid & 3;         // 0..3, n band of 32
    const int m0 = blockIdx.y * 128;
    const int n0 = blockIdx.x * 128;

    float acc[4][4][4];
#pragma unroll
    for (int i = 0; i < 4; i++)
#pragma unroll
        for (int j = 0; j < 4; j++)
#pragma unroll
            for (int k = 0; k < 4; k++) acc[i][j][k] = 0.f;

    const bf16* Abase = A + (size_t)m0 * 512;
    const bf16* Bbase = Bpk + (size_t)n0 * 1024;

    auto load_chunk = [&](int c, int buf) {
        uint32_t ab = sb + buf * 16384;
        uint32_t bb = sb + 32768 + buf * 32768;
        const bf16* As = Abase + c * 64;
        const bf16* Bs = Bbase + c * 128;
#pragma unroll
        for (int it = 0; it < 12; ++it) {
            int u = tid + it * 256;              // 0..3071
            if (u < 1024) {                      // A: 128 rows x 8 units
                int r = u >> 3, q = u & 7;
                cp16(ab + SWZ(r * 128 + q * 16), As + (size_t)r * 512 + q * 8);
            } else {                             // B: 128 rows x 16 units
                int v = u - 1024;
                int r = v >> 4, q = v & 15;
                int sub = q >> 3, qi = q & 7;
                cp16(bb + sub * 16384 + SWZ(r * 128 + qi * 16),
                     Bs + (size_t)r * 1024 + sub * 64 + qi * 8);
            }
        }
        CP_COMMIT();
    };

    load_chunk(0, 0);

    for (int c = 0; c < 8; ++c) {
        CP_WAIT(0);
        __syncthreads();
        if (c < 7) load_chunk(c + 1, (c + 1) & 1);

        const int buf = c & 1;
        const uint32_t ab = sb + buf * 16384;
#pragma unroll
        for (int sub = 0; sub < 2; ++sub) {
            const uint32_t bb = sb + 32768 + buf * 32768 + sub * 16384;
#pragma unroll
            for (int ks = 0; ks < 2; ++ks) {
                uint32_t bfr[2][4][2];
                const int brow0 = wn * 32 + (lane & 7);
                const int bsel = (lane >> 3) & 1;
#pragma unroll
                for (int pl = 0; pl < 2; ++pl)
#pragma unroll
                    for (int nt = 0; nt < 4; ++nt) {
                        int row = brow0 + nt * 8;
                        int seg = pl * 4 + ks * 2 + bsel;
                        LDSM_X2(bfr[pl][nt][0], bfr[pl][nt][1],
                                bb + row * 128 + ((seg ^ (row & 7)) << 4));
                    }
#pragma unroll
                for (int mt = 0; mt < 4; ++mt) {
                    uint32_t afr[4];
                    const int arow = wm * 64 + mt * 16 + (lane & 15);
                    const int asel = lane >> 4;
                    int seg = sub * 4 + ks * 2 + asel;
                    LDSM_X4(afr[0], afr[1], afr[2], afr[3],
                            ab + arow * 128 + ((seg ^ (arow & 7)) << 4));
#pragma unroll
                    for (int nt = 0; nt < 4; ++nt)
                        MMA_BF16(acc[mt][nt], afr, bfr[0][nt]);   // A*Whi
#pragma unroll
                    for (int nt = 0; nt < 4; ++nt)
                        MMA_BF16(acc[mt][nt], afr, bfr[1][nt]);   // A*Wlo
                }
            }
        }
        __syncthreads();
    }

    // epilogue: bias + relu -> plain bf16 h2
    const int r0 = wm * 64 + (lane >> 2);
    const int c0 = wn * 32 + (lane & 3) * 2;
#pragma unroll
    for (int mt = 0; mt < 4; ++mt)
#pragma unroll
        for (int nt = 0; nt < 4; ++nt) {
            const int gc = n0 + c0 + nt * 8;
            const float bb0 = __ldg(bias + gc);
            const float bb1 = __ldg(bias + gc + 1);
#pragma unroll
            for (int h = 0; h < 2; ++h) {
                const int row = m0 + r0 + mt * 16 + 8 * h;
                float v0 = fmaxf(acc[mt][nt][2 * h] + bb0, 0.f);
                float v1 = fmaxf(acc[mt][nt][2 * h + 1] + bb1, 0.f);
                *(bf162*)(O + (size_t)row * 512 + gc) =
                    __halves2bfloat162(__float2bfloat16(v0), __float2bfloat16(v1));
            }
        }
}

// ---------------- GEMM3 (R15-proven): plain A, split W3, N-tile 96 ----------
// smem: A0@0(16K), A1@16K, B0@32K(24K), B1@56K; total 80K (2 CTAs/SM).
__global__ __launch_bounds__(256, 2) void gemm3_mmt(
    const bf16* __restrict__ A, const bf16* __restrict__ Bpk,
    const float* __restrict__ bias, float* __restrict__ dst)
{
    extern __shared__ char smem[];
    const uint32_t sb = smem_u32(smem);
    const int tid = threadIdx.x;
    const int lane = tid & 31;
    const int wid = tid >> 5;
    const int wm = wid >> 2;        // 0..1 (m band of 64)
    const int wn = wid & 3;         // 0..3 (n band of 24)
    const int m0 = blockIdx.y * 128;

    float acc[4][3][4];
#pragma unroll
    for (int i = 0; i < 4; i++)
#pragma unroll
        for (int j = 0; j < 3; j++)
#pragma unroll
            for (int k = 0; k < 4; k++) acc[i][j][k] = 0.f;

    const bf16* Abase = A + (size_t)m0 * 512;

    auto load_chunk = [&](int c, int buf) {
        uint32_t ab = sb + buf * 16384;
        uint32_t bb = sb + 32768 + buf * 24576;
        const bf16* As = Abase + c * 64;
        const bf16* Bs = Bpk + c * 128;
#pragma unroll
        for (int it = 0; it < 10; ++it) {
            int u = tid + it * 256;              // 0..2559
            if (u < 1024) {                      // A: 128 rows x 8 units
                int r = u >> 3, q = u & 7;
                cp16(ab + SWZ(r * 128 + q * 16), As + (size_t)r * 512 + q * 8);
            } else {                             // B: 96 rows x 16 units
                int v = u - 1024;
                int r = v >> 4, q = v & 15;
                int sub = q >> 3, qi = q & 7;
                cp16(bb + sub * 12288 + SWZ(r * 128 + qi * 16),
                     Bs + (size_t)r * 1024 + sub * 64 + qi * 8);
            }
        }
        CP_COMMIT();
    };

    load_chunk(0, 0);

    for (int c = 0; c < 8; ++c) {
        CP_WAIT(0);
        __syncthreads();
        if (c < 7) load_chunk(c + 1, (c + 1) & 1);

        const int buf = c & 1;
        const uint32_t ab = sb + buf * 16384;
#pragma unroll
        for (int sub = 0; sub < 2; ++sub) {
            const uint32_t bb = sb + 32768 + buf * 24576 + sub * 12288;
#pragma unroll
            for (int ks = 0; ks < 2; ++ks) {
                uint32_t bfr[2][3][2];
                const int brow0 = wn * 24 + (lane & 7);
                const int bsel = (lane >> 3) & 1;
#pragma unroll
                for (int pl = 0; pl < 2; ++pl)
#pragma unroll
                    for (int nt = 0; nt < 3; ++nt) {
                        int row = brow0 + nt * 8;
                        int seg = pl * 4 + ks * 2 + bsel;
                        LDSM_X2(bfr[pl][nt][0], bfr[pl][nt][1],
                                bb + row * 128 + ((seg ^ (row & 7)) << 4));
                    }
#pragma unroll
                for (int mt = 0; mt < 4; ++mt) {
                    uint32_t afr[4];
                    const int arow = wm * 64 + mt * 16 + (lane & 15);
                    const int asel = lane >> 4;
                    int seg = sub * 4 + ks * 2 + asel;
                    LDSM_X4(afr[0], afr[1], afr[2], afr[3],
                            ab + arow * 128 + ((seg ^ (arow & 7)) << 4));
#pragma unroll
                    for (int nt = 0; nt < 3; ++nt)
                        MMA_BF16(acc[mt][nt], afr, bfr[0][nt]);   // A*hi
#pragma unroll
                    for (int nt = 0; nt < 3; ++nt)
                        MMA_BF16(acc[mt][nt], afr, bfr[1][nt]);   // A*lo
                }
            }
        }
        __syncthreads();
    }

    // ---- epilogue: softplus (MUFU exp/log) -> smem stage (pitch 81) ----
    const int r0 = wm * 64 + (lane >> 2);
    const int c0 = wn * 24 + (lane & 3) * 2;
    float* stage = (float*)smem;
#pragma unroll
    for (int mt = 0; mt < 4; ++mt)
#pragma unroll
        for (int nt = 0; nt < 3; ++nt) {
            const int col = c0 + nt * 8;
            if (col >= 80) continue;
#pragma unroll
            for (int h = 0; h < 2; ++h) {
                const int row = r0 + mt * 16 + 8 * h;
                if (col < OUTC)
                    stage[row * 81 + col] =
                        softplusf(acc[mt][nt][2 * h] + __ldg(bias + col));
                if (col + 1 < OUTC)
                    stage[row * 81 + col + 1] =
                        softplusf(acc[mt][nt][2 * h + 1] + __ldg(bias + col + 1));
            }
        }
    __syncthreads();

    // ---- MMT: per-(row, ii) items; Li hoisted to registers; float4 stores --
    for (int item = tid; item < 128 * 12; item += 256) {
        const int r = item / 12;
        const int ii = item - r * 12;
        const float* Lr = stage + r * 81;
        const float* Lip = Lr + ((ii * (ii + 1)) >> 1);
        float li[12];
#pragma unroll
        for (int j = 0; j < 12; ++j) li[j] = (j <= ii) ? Lip[j] : 0.f;
        __align__(16) float o[12];
#pragma unroll
        for (int kk = 0; kk < 12; ++kk) {
            const float* Lk = Lr + ((kk * (kk + 1)) >> 1);
            const int mn = ii < kk ? ii : kk;
            float a = 0.f;
            for (int j = 0; j <= mn; ++j) a = fmaf(li[j], Lk[j], a);
            o[kk] = a;
        }
        float* drow = dst + (size_t)(m0 + r) * 144 + ii * 12;
        *(float4*)(drow)     = ((float4*)o)[0];
        *(float4*)(drow + 4) = ((float4*)o)[1];
        *(float4*)(drow + 8) = ((float4*)o)[2];
    }
    if (tid < 128)
        dst[(size_t)BATCH * 144 + m0 + tid] = stage[tid * 81 + TRI];
}

// ---------------- launch ----------------------------------------------------
extern "C" void kernel_launch(void* const* d_in, const int* in_sizes, int n_in,
                              void* d_out, int out_size)
{
    const float* x  = (const float*)d_in[0];
    const float* W1 = (const float*)d_in[1];
    const float* b1 = (const float*)d_in[2];
    const float* W2 = (const float*)d_in[3];
    const float* b2 = (const float*)d_in[4];
    const float* W3 = (const float*)d_in[5];
    const float* b3 = (const float*)d_in[6];
    float* out = (float*)d_out;

    bf16 *h1, *h2, *w2pk, *w3pk;
    cudaGetSymbolAddress((void**)&h1, g_h1);
    cudaGetSymbolAddress((void**)&h2, g_h2);
    cudaGetSymbolAddress((void**)&w2pk, g_w2pk);
    cudaGetSymbolAddress((void**)&w3pk, g_w3pk);

    conv_w2<<<(HID * HID) / 256, 256>>>(W2);
    conv_w3<<<(96 * HID) / 256, 256>>>(W3);
    l1_kernel<<<BATCH / 256, 256>>>(x, W1, b1, h1);

    constexpr int SMEM2 = 98304;         // 2x16K A + 2x32K B
    constexpr int SMEM3 = 81920;         // 2x16K A + 2x24K B
    cudaFuncSetAttribute(gemm2,
                         cudaFuncAttributeMaxDynamicSharedMemorySize, SMEM2);
    cudaFuncSetAttribute(gemm3_mmt,
                         cudaFuncAttributeMaxDynamicSharedMemorySize, SMEM3);

    gemm2<<<dim3(4, BATCH / 128), 256, SMEM2>>>(h1, w2pk, b2, h2);
    gemm3_mmt<<<dim3(1, BATCH / 128), 256, SMEM3>>>(h2, w3pk, b3, out);
}